// round 7
// baseline (speedup 1.0000x reference)
#include <cuda_runtime.h>

#define MAXN 6016
#define NB   94      // max number of 64-box blocks
typedef unsigned long long u64;

// Scratch (device globals: allocation is banned; zero-initialized at load)
__device__ float4 g_sboxes[MAXN];
__device__ int    g_rank[MAXN];
__device__ u64    g_plist[MAXN];                // packed (score_bits<<32)|idx, prefix boxes
__device__ u64    g_maskT[(size_t)NB * MAXN];   // TRANSPOSED: [word][row]
__device__ int    g_cnt;  // #prefix boxes; reset to 0 at end of scan_kernel each run

// smem ring: 4 slots x NB columns x 64 rows (u64)  + remv[NB] + keep[NB]
#define SLOT_U64   (NB * 64)
#define SMEM_U64   (4 * SLOT_U64 + 2 * NB)
#define SMEM_BYTES (SMEM_U64 * 8)

#define SWEEP_WARPS 16
#define SCAN_THREADS ((SWEEP_WARPS + 1) * 32)   // 544

__device__ __forceinline__ unsigned smem_u32(const void* p) {
    return (unsigned)__cvta_generic_to_shared(p);
}
__device__ __forceinline__ void cp_async16(unsigned dst, const u64* src) {
    asm volatile("cp.async.cg.shared.global [%0], [%1], 16;" :: "r"(dst), "l"(src));
}
#define CP_COMMIT() asm volatile("cp.async.commit_group;" ::: "memory")
#define CP_WAIT1()  asm volatile("cp.async.wait_group 1;" ::: "memory")

// ---------------------------------------------------------------------------
// 0) Compact prefix boxes (s >= 0.6) into g_plist. Order is nondeterministic
//    but all downstream results are exact functions of the set, not the order.
// ---------------------------------------------------------------------------
__global__ void compact_kernel(const float* __restrict__ scores, int n) {
    int i = blockIdx.x * blockDim.x + threadIdx.x;
    if (i >= n) return;
    float s = scores[i];
    if (s >= 0.6f) {
        int p = atomicAdd(&g_cnt, 1);
        g_plist[p] = ((u64)__float_as_uint(s) << 32) | (unsigned)i;
    }
}

// ---------------------------------------------------------------------------
// 1) Rank within the prefix subset (== global rank for prefix boxes).
//    One warp per list entry; integer compares (positive floats are
//    bit-monotonic). Scatter box to its rank slot.
// ---------------------------------------------------------------------------
__global__ void rank_kernel(const float* __restrict__ boxes, int n) {
    const int w    = (blockIdx.x * blockDim.x + threadIdx.x) >> 5;
    const int lane = threadIdx.x & 31;
    const int m = g_cnt;
    if (w >= m) return;
    const u64 me = g_plist[w];
    const unsigned sb = (unsigned)(me >> 32);
    const unsigned ib = (unsigned)me;
    int cnt = 0;
    for (int j = lane; j < m; j += 32) {
        u64 e = g_plist[j];
        unsigned sj = (unsigned)(e >> 32);
        unsigned ij = (unsigned)e;
        cnt += (int)((sj > sb) | ((sj == sb) & (ij < ib)));
    }
    #pragma unroll
    for (int o = 16; o; o >>= 1) cnt += __shfl_down_sync(0xffffffffu, cnt, o);
    if (lane == 0) {
        g_sboxes[cnt] = ((const float4*)boxes)[ib];
        g_rank[ib]    = cnt;
    }
}

// ---------------------------------------------------------------------------
// 2) Suppression mask on the prefix, TRANSPOSED: g_maskT[cb][row].
//    Division-free exact threshold: iou>0.5 <=> fma(-0.5,uni,inter)>0.
// ---------------------------------------------------------------------------
__global__ void mask_kernel(int n) {
    int m = g_cnt; if (m > n) m = n;
    const int mb = (m + 63) >> 6;
    const int rb = blockIdx.y, cb = blockIdx.x;
    if (cb < rb || rb >= mb || cb >= mb) return;
    const int t = threadIdx.x;                   // 0..63

    __shared__ float4 cbox[64];                  // {cz, cw, -cx, -cy}
    __shared__ float  carea[64];
    const int col0 = cb * 64;
    if (col0 + t < m) {
        float4 c = g_sboxes[col0 + t];
        cbox[t]  = make_float4(c.z, c.w, -c.x, -c.y);
        carea[t] = (c.z - c.x) * (c.w - c.y);
    } else {
        cbox[t]  = make_float4(-1e30f, -1e30f, -1e30f, -1e30f);  // -> IoU 0
        carea[t] = 0.f;
    }
    __syncthreads();

    const int row = rb * 64 + t;
    if (row >= m) return;

    const float4 b   = g_sboxes[row];
    const float  bz  = b.z,  bw  = b.w;
    const float  nbx = -b.x, nby = -b.y;
    const float  barea = (b.z - b.x) * (b.w - b.y);

    u64 bits = 0ULL;
    #pragma unroll
    for (int k = 0; k < 64; k++) {
        float4 c  = cbox[k];
        float iw  = fmaxf(fminf(bz, c.x) + fminf(nbx, c.z), 0.f);
        float ih  = fmaxf(fminf(bw, c.y) + fminf(nby, c.w), 0.f);
        float inter = iw * ih;
        float uni   = (barea + carea[k]) - inter;
        if (fmaf(-0.5f, uni, inter) > 0.f) bits |= (1ULL << k);
    }
    if (cb == rb) bits &= ((~1ULL) << t);        // keep only cols > row
    g_maskT[(size_t)cb * MAXN + row] = bits;
}

// ---------------------------------------------------------------------------
// 3) Greedy scan + finalize, one CTA / 17 warps, ONE barrier per block:
//    warp 16: resolve(b) from smem slice; inline contribution of block b to
//             column b+1 so the next resolve never waits on sweep warps.
//    warps 0..15: cp.async-issue block b+2's column slices into 4-slot smem
//             ring; lagged sweep of block b-1 into cols >= b+1 from smem.
//    Tail: fused finalize + g_cnt reset for the next graph replay.
// ---------------------------------------------------------------------------
__global__ void scan_kernel(const float* __restrict__ scores,
                            float* __restrict__ out, int n) {
    extern __shared__ u64 sbuf[];
    u64* remv = sbuf + 4 * SLOT_U64;
    u64* keep = remv + NB;
    const int t = threadIdx.x;
    const int warp = t >> 5, lane = t & 31;
    int m = g_cnt; if (m > n) m = n;
    const int mb = (m + 63) >> 6;

    if (t < NB) { remv[t] = 0ULL; keep[t] = 0ULL; }
    __syncthreads();   // also orders everyone's g_cnt read before the tail reset

    // Priming: blocks 0 and 1 into slots 0,1 (cols >= X)
    if (warp < SWEEP_WARPS) {
        #pragma unroll
        for (int X = 0; X <= 1; X++) {
            if (X < mb) {
                for (int j = X + warp; j < mb; j += SWEEP_WARPS) {
                    u64* dst = sbuf + (size_t)(X & 3) * SLOT_U64 + j * 64 + 2 * lane;
                    cp_async16(smem_u32(dst),
                               g_maskT + (size_t)j * MAXN + X * 64 + 2 * lane);
                }
            }
            CP_COMMIT();
        }
        CP_WAIT1();
    }
    __syncthreads();

    for (int b = 0; b < mb; b++) {
        if (warp == SWEEP_WARPS) {
            const u64* dcol = sbuf + (size_t)(b & 3) * SLOT_U64 + b * 64;
            u64 d0 = dcol[2 * lane], d1 = dcol[2 * lane + 1];
            u64 nzme = ((u64)(d0 != 0ULL) << (2 * lane))
                     | ((u64)(d1 != 0ULL) << (2 * lane + 1));
            unsigned nlo = __reduce_or_sync(0xffffffffu, (unsigned)nzme);
            unsigned nhi = __reduce_or_sync(0xffffffffu, (unsigned)(nzme >> 32));
            u64 kept = 0ULL;
            if (lane == 0) {
                u64 supp = remv[b];
                const int vr = m - b * 64;
                const u64 valid = (vr >= 64) ? ~0ULL : ((1ULL << vr) - 1ULL);
                u64 rem = ((u64)nlo | ((u64)nhi << 32)) & ~supp & valid;
                while (rem) {
                    const int i = __ffsll((long long)rem) - 1;
                    rem &= rem - 1ULL;
                    if (!((supp >> i) & 1ULL)) {
                        supp |= dcol[i];
                        rem  &= ~supp;
                    }
                }
                kept = ~supp & valid;
                keep[b] = kept;
            }
            kept = __shfl_sync(0xffffffffu, kept, 0);
            if (b + 1 < mb) {  // inline: block b's contribution to column b+1
                const u64* ccol = sbuf + (size_t)(b & 3) * SLOT_U64 + (b + 1) * 64;
                u64 a0 = ccol[2 * lane]     & (0ULL - ((kept >> (2 * lane))     & 1ULL));
                u64 a1 = ccol[2 * lane + 1] & (0ULL - ((kept >> (2 * lane + 1)) & 1ULL));
                u64 acc = a0 | a1;
                unsigned lo = __reduce_or_sync(0xffffffffu, (unsigned)acc);
                unsigned hi = __reduce_or_sync(0xffffffffu, (unsigned)(acc >> 32));
                if (lane == 0) atomicOr(&remv[b + 1], (u64)lo | ((u64)hi << 32));
            }
        } else {
            // issue block b+2 slices into slot (b+2)&3
            const int X = b + 2;
            if (X < mb) {
                for (int j = X + warp; j < mb; j += SWEEP_WARPS) {
                    u64* dst = sbuf + (size_t)(X & 3) * SLOT_U64 + j * 64 + 2 * lane;
                    cp_async16(smem_u32(dst),
                               g_maskT + (size_t)j * MAXN + X * 64 + 2 * lane);
                }
            }
            CP_COMMIT();
            // lagged sweep: block b-1 -> columns >= b+1 (smem-resident)
            if (b >= 1) {
                const u64 kp = keep[b - 1];
                const u64 m0 = 0ULL - ((kp >> (2 * lane))     & 1ULL);
                const u64 m1 = 0ULL - ((kp >> (2 * lane + 1)) & 1ULL);
                const u64* s = sbuf + (size_t)((b - 1) & 3) * SLOT_U64;
                for (int j = b + 1 + warp; j < mb; j += SWEEP_WARPS) {
                    u64 acc = (s[j * 64 + 2 * lane] & m0)
                            | (s[j * 64 + 2 * lane + 1] & m1);
                    unsigned lo = __reduce_or_sync(0xffffffffu, (unsigned)acc);
                    unsigned hi = __reduce_or_sync(0xffffffffu, (unsigned)(acc >> 32));
                    if (lane == 0) atomicOr(&remv[j], (u64)lo | ((u64)hi << 32));
                }
            }
            CP_WAIT1();   // slot for block b+1 complete before next iteration
        }
        __syncthreads();
    }

    // Fused finalize: out[i] = s if (s >= 0.6 && kept) else 0
    for (int i = t; i < n; i += SCAN_THREADS) {
        float s = scores[i];
        float v = 0.0f;
        if (s >= 0.6f) {
            int r = g_rank[i];
            if ((keep[r >> 6] >> (r & 63)) & 1ULL) v = s;
        }
        out[i] = v;
    }

    if (t == 0) g_cnt = 0;   // reset for next graph replay (idempotent cycle)
}

// ---------------------------------------------------------------------------
extern "C" void kernel_launch(void* const* d_in, const int* in_sizes, int n_in,
                              void* d_out, int out_size) {
    const float* boxes  = (const float*)d_in[0];
    const float* scores = (const float*)d_in[1];
    const int n = in_sizes[1];                 // 6000

    cudaFuncSetAttribute(scan_kernel,
                         cudaFuncAttributeMaxDynamicSharedMemorySize, SMEM_BYTES);

    compact_kernel<<<(n + 255) / 256, 256>>>(scores, n);

    rank_kernel<<<(n * 32 + 255) / 256, 256>>>(boxes, n);

    dim3 grid(NB, NB);
    mask_kernel<<<grid, 64>>>(n);

    scan_kernel<<<1, SCAN_THREADS, SMEM_BYTES>>>(scores, (float*)d_out, n);
}

// round 8
// speedup vs baseline: 1.0832x; 1.0832x over previous
#include <cuda_runtime.h>

#define MAXN 6016
#define NB   94      // max number of 64-box blocks
#define TRI  (NB * (NB + 1) / 2)                // 4465 triangular tiles
typedef unsigned long long u64;

// Scratch (device globals: allocation is banned; zero-initialized at load)
__device__ float4 g_sboxes[MAXN];
__device__ int    g_rank[MAXN];
__device__ u64    g_plist[MAXN];                // packed (score_bits<<32)|idx
__device__ u64    g_maskT[(size_t)NB * MAXN];   // TRANSPOSED: [word][row]
__device__ int    g_cnt;  // #prefix boxes; reset at end of scan_kernel each run

// smem ring: 4 slots x NB columns x 64 rows (u64)  + remv[NB] + keep[NB]
#define SLOT_U64   (NB * 64)
#define SMEM_U64   (4 * SLOT_U64 + 2 * NB)
#define SMEM_BYTES (SMEM_U64 * 8)

#define SWEEP_WARPS 31
#define SCAN_THREADS 1024

__device__ __forceinline__ unsigned smem_u32(const void* p) {
    return (unsigned)__cvta_generic_to_shared(p);
}
__device__ __forceinline__ void cp_async16(unsigned dst, const u64* src) {
    asm volatile("cp.async.cg.shared.global [%0], [%1], 16;" :: "r"(dst), "l"(src));
}
#define CP_COMMIT() asm volatile("cp.async.commit_group;" ::: "memory")
#define CP_WAIT1()  asm volatile("cp.async.wait_group 1;" ::: "memory")

// ---------------------------------------------------------------------------
// 0) Compact prefix boxes (s >= 0.6) into g_plist. Order nondeterministic;
//    all downstream results are exact functions of the set, not the order.
// ---------------------------------------------------------------------------
__global__ void compact_kernel(const float* __restrict__ scores, int n) {
    int i = blockIdx.x * blockDim.x + threadIdx.x;
    if (i >= n) return;
    float s = scores[i];
    if (s >= 0.6f) {
        int p = atomicAdd(&g_cnt, 1);
        g_plist[p] = ((u64)__float_as_uint(s) << 32) | (unsigned)i;
    }
}

// ---------------------------------------------------------------------------
// 1) Rank within the prefix subset (== global rank for prefix boxes).
//    One warp per entry; integer compares (positive floats bit-monotonic).
// ---------------------------------------------------------------------------
__global__ void rank_kernel(const float* __restrict__ boxes, int n) {
    const int w    = (blockIdx.x * blockDim.x + threadIdx.x) >> 5;
    const int lane = threadIdx.x & 31;
    const int m = g_cnt;
    if (w >= m) return;
    const u64 me = g_plist[w];
    const unsigned sb = (unsigned)(me >> 32);
    const unsigned ib = (unsigned)me;
    int cnt = 0;
    for (int j = lane; j < m; j += 32) {
        u64 e = g_plist[j];
        unsigned sj = (unsigned)(e >> 32);
        unsigned ij = (unsigned)e;
        cnt += (int)((sj > sb) | ((sj == sb) & (ij < ib)));
    }
    #pragma unroll
    for (int o = 16; o; o >>= 1) cnt += __shfl_down_sync(0xffffffffu, cnt, o);
    if (lane == 0) {
        g_sboxes[cnt] = ((const float4*)boxes)[ib];
        g_rank[ib]    = cnt;
    }
}

// ---------------------------------------------------------------------------
// 2) Suppression mask on the prefix, TRANSPOSED: g_maskT[cb][row].
//    Triangular 1D grid (cb >= rb only). Division-free exact threshold.
// ---------------------------------------------------------------------------
__device__ __forceinline__ int tri_start(int r) {   // first linear idx of row r
    return r * NB - (r * (r - 1)) / 2;
}
__global__ void mask_kernel(int n) {
    int m = g_cnt; if (m > n) m = n;
    const int mb = (m + 63) >> 6;

    // linear tile -> (rb, cb) with cb >= rb
    const int p = blockIdx.x;
    int rb = (int)((2.0f * NB + 1.0f
                    - sqrtf((2.0f * NB + 1.0f) * (2.0f * NB + 1.0f) - 8.0f * p)) * 0.5f);
    if (rb < 0) rb = 0;
    while (rb + 1 <= NB - 1 && tri_start(rb + 1) <= p) rb++;
    while (rb > 0 && tri_start(rb) > p) rb--;
    const int cb = rb + (p - tri_start(rb));

    if (rb >= mb || cb >= mb) return;
    const int t = threadIdx.x;                   // 0..63

    __shared__ float4 cbox[64];                  // {cz, cw, -cx, -cy}
    __shared__ float  carea[64];
    const int col0 = cb * 64;
    if (col0 + t < m) {
        float4 c = g_sboxes[col0 + t];
        cbox[t]  = make_float4(c.z, c.w, -c.x, -c.y);
        carea[t] = (c.z - c.x) * (c.w - c.y);
    } else {
        cbox[t]  = make_float4(-1e30f, -1e30f, -1e30f, -1e30f);  // -> IoU 0
        carea[t] = 0.f;
    }
    __syncthreads();

    const int row = rb * 64 + t;
    if (row >= m) return;

    const float4 b   = g_sboxes[row];
    const float  bz  = b.z,  bw  = b.w;
    const float  nbx = -b.x, nby = -b.y;
    const float  barea = (b.z - b.x) * (b.w - b.y);

    u64 bits = 0ULL;
    #pragma unroll
    for (int k = 0; k < 64; k++) {
        float4 c  = cbox[k];
        float iw  = fmaxf(fminf(bz, c.x) + fminf(nbx, c.z), 0.f);
        float ih  = fmaxf(fminf(bw, c.y) + fminf(nby, c.w), 0.f);
        float inter = iw * ih;
        float uni   = (barea + carea[k]) - inter;
        if (fmaf(-0.5f, uni, inter) > 0.f) bits |= (1ULL << k);
    }
    if (cb == rb) bits &= ((~1ULL) << t);        // keep only cols > row
    g_maskT[(size_t)cb * MAXN + row] = bits;
}

// ---------------------------------------------------------------------------
// 3) Greedy scan + finalize, one CTA / 32 warps, ONE barrier per block:
//    warp 31: resolve(b) from smem slice; block b's contribution to column
//             b+1 is computed in-warp and CARRIED IN REGISTERS to iteration
//             b+1 (no smem atomic on the serial chain).
//    warps 0..30: cp.async-issue block b+2's slices into 4-slot smem ring;
//             lagged sweep of block b-1 into cols >= b+1 from smem.
// ---------------------------------------------------------------------------
__global__ void scan_kernel(const float* __restrict__ scores,
                            float* __restrict__ out, int n) {
    extern __shared__ u64 sbuf[];
    u64* remv = sbuf + 4 * SLOT_U64;
    u64* keep = remv + NB;
    const int t = threadIdx.x;
    const int warp = t >> 5, lane = t & 31;
    int m = g_cnt; if (m > n) m = n;
    const int mb = (m + 63) >> 6;

    if (t < NB) { remv[t] = 0ULL; keep[t] = 0ULL; }
    __syncthreads();   // orders everyone's g_cnt read before the tail reset

    // Priming: blocks 0 and 1 into slots 0,1 (cols >= X)
    if (warp < SWEEP_WARPS) {
        #pragma unroll
        for (int X = 0; X <= 1; X++) {
            if (X < mb) {
                for (int j = X + warp; j < mb; j += SWEEP_WARPS) {
                    u64* dst = sbuf + (size_t)(X & 3) * SLOT_U64 + j * 64 + 2 * lane;
                    cp_async16(smem_u32(dst),
                               g_maskT + (size_t)j * MAXN + X * 64 + 2 * lane);
                }
            }
            CP_COMMIT();
        }
        CP_WAIT1();
    }
    __syncthreads();

    u64 carry = 0ULL;   // resolve warp: block b-1's contribution to column b

    for (int b = 0; b < mb; b++) {
        if (warp == SWEEP_WARPS) {
            const u64* dcol = sbuf + (size_t)(b & 3) * SLOT_U64 + b * 64;
            u64 d0 = dcol[2 * lane], d1 = dcol[2 * lane + 1];
            u64 nzme = ((u64)(d0 != 0ULL) << (2 * lane))
                     | ((u64)(d1 != 0ULL) << (2 * lane + 1));
            unsigned nlo = __reduce_or_sync(0xffffffffu, (unsigned)nzme);
            unsigned nhi = __reduce_or_sync(0xffffffffu, (unsigned)(nzme >> 32));
            u64 kept = 0ULL;
            if (lane == 0) {
                u64 supp = remv[b] | carry;
                const int vr = m - b * 64;
                const u64 valid = (vr >= 64) ? ~0ULL : ((1ULL << vr) - 1ULL);
                u64 rem = ((u64)nlo | ((u64)nhi << 32)) & ~supp & valid;
                while (rem) {
                    const int i = __ffsll((long long)rem) - 1;
                    rem &= rem - 1ULL;
                    if (!((supp >> i) & 1ULL)) {
                        supp |= dcol[i];
                        rem  &= ~supp;
                    }
                }
                kept = ~supp & valid;
                keep[b] = kept;
            }
            kept = __shfl_sync(0xffffffffu, kept, 0);
            carry = 0ULL;
            if (b + 1 < mb) {  // block b -> column b+1, kept in registers
                const u64* ccol = sbuf + (size_t)(b & 3) * SLOT_U64 + (b + 1) * 64;
                u64 a0 = ccol[2 * lane]     & (0ULL - ((kept >> (2 * lane))     & 1ULL));
                u64 a1 = ccol[2 * lane + 1] & (0ULL - ((kept >> (2 * lane + 1)) & 1ULL));
                u64 acc = a0 | a1;
                unsigned lo = __reduce_or_sync(0xffffffffu, (unsigned)acc);
                unsigned hi = __reduce_or_sync(0xffffffffu, (unsigned)(acc >> 32));
                carry = (u64)lo | ((u64)hi << 32);   // uniform across warp
            }
        } else {
            // issue block b+2 slices into slot (b+2)&3
            const int X = b + 2;
            if (X < mb) {
                for (int j = X + warp; j < mb; j += SWEEP_WARPS) {
                    u64* dst = sbuf + (size_t)(X & 3) * SLOT_U64 + j * 64 + 2 * lane;
                    cp_async16(smem_u32(dst),
                               g_maskT + (size_t)j * MAXN + X * 64 + 2 * lane);
                }
            }
            CP_COMMIT();
            // lagged sweep: block b-1 -> columns >= b+1 (smem-resident)
            if (b >= 1) {
                const u64 kp = keep[b - 1];
                const u64 m0 = 0ULL - ((kp >> (2 * lane))     & 1ULL);
                const u64 m1 = 0ULL - ((kp >> (2 * lane + 1)) & 1ULL);
                const u64* s = sbuf + (size_t)((b - 1) & 3) * SLOT_U64;
                for (int j = b + 1 + warp; j < mb; j += SWEEP_WARPS) {
                    u64 acc = (s[j * 64 + 2 * lane] & m0)
                            | (s[j * 64 + 2 * lane + 1] & m1);
                    unsigned lo = __reduce_or_sync(0xffffffffu, (unsigned)acc);
                    unsigned hi = __reduce_or_sync(0xffffffffu, (unsigned)(acc >> 32));
                    if (lane == 0) atomicOr(&remv[j], (u64)lo | ((u64)hi << 32));
                }
            }
            CP_WAIT1();   // slot for block b+1 complete before next iteration
        }
        __syncthreads();
    }

    // Fused finalize: out[i] = s if (s >= 0.6 && kept) else 0
    for (int i = t; i < n; i += SCAN_THREADS) {
        float s = scores[i];
        float v = 0.0f;
        if (s >= 0.6f) {
            int r = g_rank[i];
            if ((keep[r >> 6] >> (r & 63)) & 1ULL) v = s;
        }
        out[i] = v;
    }

    if (t == 0) g_cnt = 0;   // reset for next graph replay (idempotent cycle)
}

// ---------------------------------------------------------------------------
extern "C" void kernel_launch(void* const* d_in, const int* in_sizes, int n_in,
                              void* d_out, int out_size) {
    const float* boxes  = (const float*)d_in[0];
    const float* scores = (const float*)d_in[1];
    const int n = in_sizes[1];                 // 6000

    cudaFuncSetAttribute(scan_kernel,
                         cudaFuncAttributeMaxDynamicSharedMemorySize, SMEM_BYTES);

    compact_kernel<<<(n + 255) / 256, 256>>>(scores, n);

    rank_kernel<<<(n * 32 + 255) / 256, 256>>>(boxes, n);

    mask_kernel<<<TRI, 64>>>(n);

    scan_kernel<<<1, SCAN_THREADS, SMEM_BYTES>>>(scores, (float*)d_out, n);
}